// round 16
// baseline (speedup 1.0000x reference)
#include <cuda_runtime.h>
#include <math.h>

#define BB 2
#define CC 19
#define NN 4096
#define DD 256
#define HH 64
#define GPAD 20
#define GPADB 36                 // gram smem row stride (32 k + 4 pad)
#define GSTGB (128 * GPADB)      // floats per operand per stage
#define GST2B (2 * GSTGB)        // floats per stage
#define TSTR 132
#define KSLC 4
#define NFSL ((size_t)BB * NN * DD)
#define SCAP 128

// ---------------- scratch ----------------
__device__ float    g_aff [(size_t)BB * NN * NN];
__device__ float    g_nrm [BB * NN];
__device__ float    g_xn  [BB * NN * DD];
__device__ float    g_zT  [BB * DD * NN];
__device__ float    g_nfp [KSLC * (size_t)BB * NN * DD];
__device__ float    g_hid [BB * NN * DD];
__device__ int      g_pmax [BB * NN];
__device__ float    g_mask [BB * NN];
__device__ float    g_thr  [BB * NN];
__device__ float    g_deg  [BB * NN];
__device__ float    g_deg2 [BB * NN];
__device__ float    g_y    [BB * NN * CC];
__device__ float    g_p2   [BB * NN * CC];
__device__ float    g_spnh [BB * NN * 24];
__device__ float    g_spnl [BB * NN * 24];
__device__ unsigned g_bits [BB * NN];
__device__ int      g_sidx [(size_t)BB * NN * SCAP];
__device__ float    g_sval [(size_t)BB * NN * SCAP];
__device__ int      g_scnt [BB * NN];

// ---------------- helpers ----------------
__device__ __forceinline__ float rna_tf32(float x) {
    unsigned u;
    asm("cvt.rna.tf32.f32 %0, %1;" : "=r"(u) : "f"(x));
    return __uint_as_float(u);
}
__device__ __forceinline__ unsigned f2u(float x) { return __float_as_uint(x); }

__device__ __forceinline__ void split_tf32(float x, unsigned& hi, unsigned& lo) {
    float h = rna_tf32(x);
    hi = __float_as_uint(h);
    lo = __float_as_uint(rna_tf32(x - h));
}

__device__ __forceinline__ void mma8(float* c,
                                     unsigned a0, unsigned a1, unsigned a2, unsigned a3,
                                     unsigned b0, unsigned b1) {
    asm volatile(
        "mma.sync.aligned.m16n8k8.row.col.f32.tf32.tf32.f32 "
        "{%0,%1,%2,%3},{%4,%5,%6,%7},{%8,%9},{%0,%1,%2,%3};\n"
        : "+f"(c[0]), "+f"(c[1]), "+f"(c[2]), "+f"(c[3])
        : "r"(a0), "r"(a1), "r"(a2), "r"(a3), "r"(b0), "r"(b1));
}

__device__ __forceinline__ void cp_async16(const void* smem, const void* gmem) {
    unsigned s = (unsigned)__cvta_generic_to_shared(smem);
    asm volatile("cp.async.cg.shared.global [%0], [%1], 16;" :: "r"(s), "l"(gmem));
}

// ---------------- small kernels ----------------
__global__ void k_softmax_mask(const float* __restrict__ pred,
                               const float* __restrict__ cw) {
    int b = blockIdx.y;
    int n = blockIdx.x * 256 + threadIdx.x;
    const float* p = pred + (size_t)b * CC * NN;
    float x[CC];
    float m = -1e30f; int am = 0;
#pragma unroll
    for (int c = 0; c < CC; c++) {
        x[c] = p[c * NN + n];
        if (x[c] > m) { m = x[c]; am = c; }
    }
    float s = 0.f;
#pragma unroll
    for (int c = 0; c < CC; c++) s += expf(x[c] - m);
    float pprob = 1.0f / s;
    float cwmax = cw[0];
#pragma unroll
    for (int c = 1; c < CC; c++) cwmax = fmaxf(cwmax, cw[c]);
    float cwm = cw[am] / (cwmax + 1e-10f) * 0.95f;
    g_pmax[b * NN + n] = am;
    g_mask[b * NN + n] = (pprob >= 0.95f || pprob >= cwm) ? 1.f : 0.f;
    g_deg[b * NN + n] = 0.f;
#pragma unroll
    for (int c = 0; c < CC; c++) g_p2[((size_t)b * NN + n) * CC + c] = 0.f;
}

__global__ void k_sumsq(const float* __restrict__ feat) {
    int b = blockIdx.y;
    int n = blockIdx.x * 256 + threadIdx.x;
    const float* p = feat + (size_t)b * DD * NN + n;
    float s = 0.f;
#pragma unroll 8
    for (int d = 0; d < DD; d++) {
        float v = p[(size_t)d * NN];
        s += v * v;
    }
    g_nrm[b * NN + n] = 1.0f / (sqrtf(s) + 1e-9f);
}

__global__ void k_transpose_norm(const float* __restrict__ feat) {
    __shared__ float t[32][33];
    int b = blockIdx.z;
    int n0 = blockIdx.x * 32, d0 = blockIdx.y * 32;
#pragma unroll
    for (int k = 0; k < 4; k++) {
        int d = d0 + threadIdx.y + 8 * k, n = n0 + threadIdx.x;
        t[threadIdx.y + 8 * k][threadIdx.x] = feat[((size_t)b * DD + d) * NN + n];
    }
    __syncthreads();
#pragma unroll
    for (int k = 0; k < 4; k++) {
        int n = n0 + threadIdx.y + 8 * k, d = d0 + threadIdx.x;
        float v = t[threadIdx.x][threadIdx.y + 8 * k] * g_nrm[b * NN + n];
        g_xn[((size_t)b * NN + n) * DD + d] = v;
    }
}

// ---------------- gram: split-tf32 MMA, triangular, cp.async (k-chunk 32) ----------------
__global__ __launch_bounds__(256) void k_gram_tc() {
    if (blockIdx.x < blockIdx.y) return;
    int b = blockIdx.z;
    const float* X = g_xn + (size_t)b * NN * DD;
    float* Cc = g_aff + (size_t)b * NN * NN;
    extern __shared__ float sm[];
    int I = blockIdx.y * 128, J = blockIdx.x * 128;
    bool offdiag = (blockIdx.x != blockIdx.y);
    int tid = threadIdx.x;
    int warp = tid >> 5, lane = tid & 31;
    int wm = warp & 1, wn = warp >> 1;
    int gr = lane >> 2, gc = lane & 3;

    auto prefetch = [&](int stage, int kb) {
        float* S = sm + stage * GST2B;
#pragma unroll
        for (int it = 0; it < 4; it++) {
            int idx = tid + it * 256;
            int r = idx >> 3, k4 = (idx & 7) * 4;
            cp_async16(&S[r * GPADB + k4], &X[(size_t)(I + r) * DD + kb + k4]);
            cp_async16(&S[GSTGB + r * GPADB + k4], &X[(size_t)(J + r) * DD + kb + k4]);
        }
    };

    prefetch(0, 0);
    asm volatile("cp.async.commit_group;" ::: "memory");

    float acc[4][4][4] = {};
    for (int i = 0; i < 8; i++) {
        asm volatile("cp.async.wait_group 0;" ::: "memory");
        __syncthreads();
        if (i + 1 < 8) {
            prefetch((i + 1) & 1, (i + 1) * 32);
            asm volatile("cp.async.commit_group;" ::: "memory");
        }
        const float* S = sm + (i & 1) * GST2B;
        const float* As = S;
        const float* Bs = S + GSTGB;
#pragma unroll
        for (int ks = 0; ks < 32; ks += 8) {
            unsigned bh[4][2], bl[4][2];
#pragma unroll
            for (int nt = 0; nt < 4; nt++) {
                int n0 = (wn * 32 + nt * 8 + gr) * GPADB + ks + gc;
                split_tf32(Bs[n0], bh[nt][0], bl[nt][0]);
                split_tf32(Bs[n0 + 4], bh[nt][1], bl[nt][1]);
            }
#pragma unroll
            for (int mt = 0; mt < 4; mt++) {
                int m0 = (wm * 64 + mt * 16 + gr) * GPADB + ks + gc;
                int m1 = m0 + 8 * GPADB;
                unsigned ah0, ah1, ah2, ah3, al0, al1, al2, al3;
                split_tf32(As[m0], ah0, al0);
                split_tf32(As[m1], ah1, al1);
                split_tf32(As[m0 + 4], ah2, al2);
                split_tf32(As[m1 + 4], ah3, al3);
#pragma unroll
                for (int nt = 0; nt < 4; nt++) {
                    mma8(acc[mt][nt], ah0, ah1, ah2, ah3, bh[nt][0], bh[nt][1]);
                    mma8(acc[mt][nt], ah0, ah1, ah2, ah3, bl[nt][0], bl[nt][1]);
                    mma8(acc[mt][nt], al0, al1, al2, al3, bh[nt][0], bh[nt][1]);
                }
            }
        }
        __syncthreads();
    }
#pragma unroll
    for (int mt = 0; mt < 4; mt++)
#pragma unroll
        for (int nt = 0; nt < 4; nt++)
#pragma unroll
            for (int q = 0; q < 4; q++)
                acc[mt][nt][q] = fmaxf(acc[mt][nt][q], 0.f);
#pragma unroll
    for (int mt = 0; mt < 4; mt++) {
        int row0 = I + wm * 64 + mt * 16 + gr;
#pragma unroll
        for (int nt = 0; nt < 4; nt++) {
            int col = J + wn * 32 + nt * 8 + 2 * gc;
            *(float2*)&Cc[(size_t)row0 * NN + col] = make_float2(acc[mt][nt][0], acc[mt][nt][1]);
            *(float2*)&Cc[(size_t)(row0 + 8) * NN + col] = make_float2(acc[mt][nt][2], acc[mt][nt][3]);
        }
    }
    if (offdiag) {
#pragma unroll
        for (int h = 0; h < 2; h++) {
            __syncthreads();
            if ((wn >> 1) == h) {
                int cb = (wn & 1) * 32;
#pragma unroll
                for (int mt = 0; mt < 4; mt++) {
                    int r = wm * 64 + mt * 16 + gr;
#pragma unroll
                    for (int nt = 0; nt < 4; nt++) {
                        int c = cb + nt * 8 + 2 * gc;
                        sm[c * TSTR + r] = acc[mt][nt][0];
                        sm[(c + 1) * TSTR + r] = acc[mt][nt][1];
                        sm[c * TSTR + r + 8] = acc[mt][nt][2];
                        sm[(c + 1) * TSTR + r + 8] = acc[mt][nt][3];
                    }
                }
            }
            __syncthreads();
            for (int idx = tid; idx < 64 * 32; idx += 256) {
                int c = idx >> 5;
                int q = (idx & 31) * 4;
                float4 v = *(const float4*)&sm[c * TSTR + q];
                *(float4*)&Cc[(size_t)(J + h * 64 + c) * NN + I + q] = v;
            }
        }
    }
}

// per-row 21st-largest via byte-radix select; round-1 hist fused with load;
// fused deg + survivor list emission
__global__ void k_topk() {
    int b = blockIdx.y, row = blockIdx.x;
    const float* A = g_aff + ((size_t)b * NN + row) * NN;
    __shared__ unsigned sv[NN];
    __shared__ int hist[256];
    __shared__ unsigned s_prefix;
    __shared__ int s_k;
    __shared__ int s_cnt;
    int t = threadIdx.x;
    hist[t] = 0;
    if (t == 0) { s_prefix = 0; s_k = 21; s_cnt = 0; }
    __syncthreads();
    for (int i = t; i < NN; i += 256) {
        unsigned v = __float_as_uint(A[i]);
        sv[i] = v;
        atomicAdd(&hist[v >> 24], 1);
    }
    __syncthreads();
    // selection for shift=24
    if (t < 32) {
        int base = 255 - t * 8;
        int c[8]; int sum = 0;
#pragma unroll
        for (int j = 0; j < 8; j++) { c[j] = hist[base - j]; sum += c[j]; }
        int incl = sum;
#pragma unroll
        for (int o = 1; o < 32; o <<= 1) {
            int up = __shfl_up_sync(0xffffffffu, incl, o);
            if (t >= o) incl += up;
        }
        int excl = incl - sum;
        int kk = s_k;
        if (excl < kk && incl >= kk) {
            int run = excl;
#pragma unroll
            for (int j = 0; j < 8; j++) {
                run += c[j];
                if (run >= kk) {
                    s_prefix = (unsigned)(base - j) << 24;
                    s_k = kk - (run - c[j]);
                    break;
                }
            }
        }
    }
    __syncthreads();
#pragma unroll
    for (int shift = 16; shift >= 0; shift -= 8) {
        hist[t] = 0;
        __syncthreads();
        unsigned pfx = s_prefix;
        unsigned mask = 0xFFFFFFFFu << (shift + 8);
        for (int i = t; i < NN; i += 256) {
            unsigned v = sv[i];
            if ((v & mask) == pfx) atomicAdd(&hist[(v >> shift) & 255], 1);
        }
        __syncthreads();
        if (t < 32) {
            int base = 255 - t * 8;
            int c[8]; int sum = 0;
#pragma unroll
            for (int j = 0; j < 8; j++) { c[j] = hist[base - j]; sum += c[j]; }
            int incl = sum;
#pragma unroll
            for (int o = 1; o < 32; o <<= 1) {
                int up = __shfl_up_sync(0xffffffffu, incl, o);
                if (t >= o) incl += up;
            }
            int excl = incl - sum;
            int kk = s_k;
            if (excl < kk && incl >= kk) {
                int run = excl;
#pragma unroll
                for (int j = 0; j < 8; j++) {
                    run += c[j];
                    if (run >= kk) {
                        s_prefix = pfx | ((unsigned)(base - j) << shift);
                        s_k = kk - (run - c[j]);
                        break;
                    }
                }
            }
        }
        __syncthreads();
    }
    unsigned thr_bits = s_prefix;
    if (t == 0) g_thr[b * NN + row] = __uint_as_float(thr_bits);
    int*   SI = g_sidx + ((size_t)b * NN + row) * SCAP;
    float* SV = g_sval + ((size_t)b * NN + row) * SCAP;
    float s = 0.f;
    for (int i = t; i < NN; i += 256) {
        unsigned v = sv[i];
        if (v >= thr_bits) {
            float val = __uint_as_float(v);
            s += val;
            atomicAdd(&g_deg[b * NN + i], val);
            int slot = atomicAdd(&s_cnt, 1);
            if (slot < SCAP) { SI[slot] = i; SV[slot] = val; }
        }
    }
#pragma unroll
    for (int o = 16; o; o >>= 1) s += __shfl_down_sync(0xffffffffu, s, o);
    if ((t & 31) == 0) atomicAdd(&g_deg[b * NN + row], s);
    __syncthreads();
    if (t == 0) g_scnt[b * NN + row] = (s_cnt < SCAP) ? s_cnt : SCAP;
}

// y scale + bits signature + deg2 zero (fused)
__global__ void k_scale_y(const float* __restrict__ pred) {
    int b = blockIdx.y;
    int m = blockIdx.x * 256 + threadIdx.x;
    float d1 = rsqrtf(g_deg[b * NN + m] + 1e-10f);
    const float* p = pred + (size_t)b * CC * NN;
#pragma unroll
    for (int c = 0; c < CC; c++)
        g_y[((size_t)b * NN + m) * CC + c] = d1 * p[c * NN + m];
    unsigned bits = 0;
#pragma unroll
    for (int j = 0; j < CC; j++) {
        int L = m * CC + j;
        int w = L / (CC * HH);
        int rem = L - w * (CC * HH);
        int c = rem >> 6;
        int h = rem & 63;
        if (g_pmax[b * NN + (h << 6) + w] == c) bits |= (1u << j);
    }
    g_bits[b * NN + m] = bits;
    g_deg2[b * NN + m] = 0.f;
}

// sparse p2: warp per row; row term local, mirror term via scattered atomics
__global__ __launch_bounds__(256) void k_p2sparse() {
    int b = blockIdx.y;
    int warp = threadIdx.x >> 5, lane = threadIdx.x & 31;
    int row = blockIdx.x * 8 + warp;
    int cnt = g_scnt[b * NN + row];
    const int*   SI = g_sidx + ((size_t)b * NN + row) * SCAP;
    const float* SV = g_sval + ((size_t)b * NN + row) * SCAP;
    float* P = g_p2 + (size_t)b * NN * CC;
    const float* Y = g_y + (size_t)b * NN * CC;
    float yi = (lane < CC) ? Y[(size_t)row * CC + lane] : 0.f;
    float acc = 0.f;
    for (int sidx = 0; sidx < cnt; sidx++) {
        int j = SI[sidx];
        float a = SV[sidx];
        if (lane < CC) {
            acc += a * Y[(size_t)j * CC + lane];
            atomicAdd(&P[(size_t)j * CC + lane], a * yi);
        }
    }
    if (lane < CC) atomicAdd(&P[(size_t)row * CC + lane], acc);
}

__global__ void k_predhead(const float* __restrict__ pred,
                           const float* __restrict__ w1, const float* __restrict__ b1,
                           const float* __restrict__ w2, const float* __restrict__ b2,
                           float* __restrict__ out_pred) {
    __shared__ float W1[CC * CC], W2[CC * CC], B1[CC], B2[CC];
    int t = threadIdx.x;
    for (int i = t; i < CC * CC; i += 256) { W1[i] = w1[i]; W2[i] = w2[i]; }
    if (t < CC) { B1[t] = b1[t]; B2[t] = b2[t]; }
    __syncthreads();
    int b = blockIdx.y;
    int n = blockIdx.x * 256 + t;
    float mk = g_mask[b * NN + n];
    float wa = 0.8f - 0.6f * mk;
    float wb = 0.2f + 0.6f * mk;
    float d1n = rsqrtf(g_deg[b * NN + n] + 1e-10f);
    float v[CC];
#pragma unroll
    for (int c = 0; c < CC; c++) {
        float p2v = g_p2[((size_t)b * NN + n) * CC + c] * d1n;
        float prv = pred[((size_t)b * CC + c) * NN + n];
        v[c] = wa * p2v + wb * prv;
    }
    float t1[CC];
#pragma unroll
    for (int o = 0; o < CC; o++) {
        float s = B1[o];
#pragma unroll
        for (int c = 0; c < CC; c++) s += W1[o * CC + c] * v[c];
        t1[o] = s;
    }
    float u[CC];
    float m = -1e30f;
#pragma unroll
    for (int o = 0; o < CC; o++) {
        float s = B2[o];
#pragma unroll
        for (int c = 0; c < CC; c++) s += W2[o * CC + c] * t1[c];
        u[o] = s;
        out_pred[((size_t)b * CC + o) * NN + n] = s;
        m = fmaxf(m, s);
    }
    float sum = 0.f;
#pragma unroll
    for (int o = 0; o < CC; o++) { u[o] = expf(u[o] - m); sum += u[o]; }
    float inv = 1.0f / sum;
    float nrm = 0.f;
#pragma unroll
    for (int o = 0; o < CC; o++) { u[o] *= inv; nrm += u[o] * u[o]; }
    float rn = 1.0f / (sqrtf(nrm) + 1e-9f);
    size_t base = ((size_t)b * NN + n) * 24;
#pragma unroll
    for (int o = 0; o < CC; o++) {
        float val = u[o] * rn;
        float hi = rna_tf32(val);
        g_spnh[base + o] = hi;
        g_spnl[base + o] = rna_tf32(val - hi);
    }
#pragma unroll
    for (int o = CC; o < 24; o++) { g_spnh[base + o] = 0.f; g_spnl[base + o] = 0.f; }
}

// deg2 = rowsum(AF), AF symmetric -> triangular blocks; off-diag adds col sums
__global__ __launch_bounds__(256) void k_deg2_tc() {
    if (blockIdx.x < blockIdx.y) return;
    int b = blockIdx.z;
    int I = blockIdx.y * 128, J = blockIdx.x * 128;
    bool offdiag = (blockIdx.x != blockIdx.y);
    const float* SH = g_spnh + (size_t)b * NN * 24;
    const float* SL = g_spnl + (size_t)b * NN * 24;
    __shared__ float Bh[128][28], Bl[128][28];
    __shared__ unsigned bJ[128];
    __shared__ float degs[128];
    __shared__ float degsJ[128];
    int tid = threadIdx.x;
    for (int idx = tid; idx < 128 * 6; idx += 256) {
        int r = idx / 6, q = (idx % 6) * 4;
        *(float4*)&Bh[r][q] = *(const float4*)&SH[(size_t)(J + r) * 24 + q];
        *(float4*)&Bl[r][q] = *(const float4*)&SL[(size_t)(J + r) * 24 + q];
    }
    if (tid < 128) { bJ[tid] = g_bits[b * NN + J + tid]; degs[tid] = 0.f; degsJ[tid] = 0.f; }
    int warp = tid >> 5, lane = tid & 31;
    int wm = warp & 3, wn = warp >> 2;
    int gr = lane >> 2, gc = lane & 3;
    float ah[2][3][4], al[2][3][4];
    unsigned bi[2][2];
#pragma unroll
    for (int mt = 0; mt < 2; mt++) {
        int r0 = I + wm * 32 + mt * 16 + gr;
        bi[mt][0] = g_bits[b * NN + r0];
        bi[mt][1] = g_bits[b * NN + r0 + 8];
#pragma unroll
        for (int kc = 0; kc < 3; kc++) {
            int k = kc * 8 + gc;
            ah[mt][kc][0] = SH[(size_t)r0 * 24 + k];
            ah[mt][kc][1] = SH[(size_t)(r0 + 8) * 24 + k];
            ah[mt][kc][2] = SH[(size_t)r0 * 24 + k + 4];
            ah[mt][kc][3] = SH[(size_t)(r0 + 8) * 24 + k + 4];
            al[mt][kc][0] = SL[(size_t)r0 * 24 + k];
            al[mt][kc][1] = SL[(size_t)(r0 + 8) * 24 + k];
            al[mt][kc][2] = SL[(size_t)r0 * 24 + k + 4];
            al[mt][kc][3] = SL[(size_t)(r0 + 8) * 24 + k + 4];
        }
    }
    __syncthreads();
    float rs[2][2] = {};
#pragma unroll
    for (int nt = 0; nt < 8; nt++) {
        int nr = wn * 64 + nt * 8 + gr;
        int c0 = wn * 64 + nt * 8 + 2 * gc;
        unsigned bj0 = bJ[c0], bj1 = bJ[c0 + 1];
        float cs0 = 0.f, cs1 = 0.f;
#pragma unroll
        for (int mt = 0; mt < 2; mt++) {
            float acc[4] = {};
#pragma unroll
            for (int kc = 0; kc < 3; kc++) {
                unsigned bh0 = f2u(Bh[nr][kc * 8 + gc]), bh1 = f2u(Bh[nr][kc * 8 + gc + 4]);
                unsigned bl0 = f2u(Bl[nr][kc * 8 + gc]), bl1 = f2u(Bl[nr][kc * 8 + gc + 4]);
                unsigned h0 = f2u(ah[mt][kc][0]), h1 = f2u(ah[mt][kc][1]);
                unsigned h2 = f2u(ah[mt][kc][2]), h3 = f2u(ah[mt][kc][3]);
                unsigned l0 = f2u(al[mt][kc][0]), l1 = f2u(al[mt][kc][1]);
                unsigned l2 = f2u(al[mt][kc][2]), l3 = f2u(al[mt][kc][3]);
                mma8(acc, h0, h1, h2, h3, bh0, bh1);
                mma8(acc, h0, h1, h2, h3, bl0, bl1);
                mma8(acc, l0, l1, l2, l3, bh0, bh1);
            }
            float v0 = (bi[mt][0] & bj0) ? fmaxf(acc[0], 0.f) : 0.f;
            float v1 = (bi[mt][0] & bj1) ? fmaxf(acc[1], 0.f) : 0.f;
            float v2 = (bi[mt][1] & bj0) ? fmaxf(acc[2], 0.f) : 0.f;
            float v3 = (bi[mt][1] & bj1) ? fmaxf(acc[3], 0.f) : 0.f;
            rs[mt][0] += v0 + v1;
            rs[mt][1] += v2 + v3;
            cs0 += v0 + v2;
            cs1 += v1 + v3;
        }
        if (offdiag) {
#pragma unroll
            for (int o = 16; o >= 4; o >>= 1) {
                cs0 += __shfl_down_sync(0xffffffffu, cs0, o);
                cs1 += __shfl_down_sync(0xffffffffu, cs1, o);
            }
            if (gr == 0) {
                atomicAdd(&degsJ[c0], cs0);
                atomicAdd(&degsJ[c0 + 1], cs1);
            }
        }
    }
#pragma unroll
    for (int mt = 0; mt < 2; mt++)
#pragma unroll
        for (int h = 0; h < 2; h++) {
            float v = rs[mt][h];
            v += __shfl_down_sync(0xffffffffu, v, 2);
            v += __shfl_down_sync(0xffffffffu, v, 1);
            if (gc == 0) atomicAdd(&degs[wm * 32 + mt * 16 + gr + h * 8], v);
        }
    __syncthreads();
    if (tid < 128) {
        atomicAdd(&g_deg2[b * NN + I + tid], degs[tid]);
        if (offdiag) atomicAdd(&g_deg2[b * NN + J + tid], degsJ[tid]);
    }
}

__global__ void k_scale_zT(const float* __restrict__ feat) {
    size_t idx = (size_t)blockIdx.x * 256 + threadIdx.x;
    size_t m = idx & (NN - 1);
    size_t b = idx >> 20;
    float d2 = rsqrtf(g_deg2[b * NN + m] + 1e-10f);
    g_zT[idx] = rna_tf32(feat[idx] * d2);
}

// nf partials (split-K): g_nfp[ks] = AF[:, slice] @ z[slice, :]
__global__ __launch_bounds__(256) void k_nf_fused() {
    int zb = blockIdx.z;
    int b = zb >> 2, ksl = zb & 3;
    const float* SH = g_spnh + (size_t)b * NN * 24;
    const float* SL = g_spnl + (size_t)b * NN * 24;
    const float* Zt = g_zT + (size_t)b * DD * NN;
    __shared__ float Bh[32][28], Bl[32][28];
    __shared__ unsigned bK[32];
    __shared__ float As[128][36];
    __shared__ float Bs[128][36];
    int I = blockIdx.y * 128, J = blockIdx.x * 128;
    int tid = threadIdx.x;
    int warp = tid >> 5, lane = tid & 31;
    int wm = warp & 3, wn = warp >> 2;
    int gr = lane >> 2, gc = lane & 3;
    float ah[3][4], al[3][4];
    unsigned bi0, bi1;
    {
        int r0 = I + warp * 16 + gr;
        bi0 = g_bits[b * NN + r0];
        bi1 = g_bits[b * NN + r0 + 8];
#pragma unroll
        for (int kc = 0; kc < 3; kc++) {
            int k = kc * 8 + gc;
            ah[kc][0] = SH[(size_t)r0 * 24 + k];
            ah[kc][1] = SH[(size_t)(r0 + 8) * 24 + k];
            ah[kc][2] = SH[(size_t)r0 * 24 + k + 4];
            ah[kc][3] = SH[(size_t)(r0 + 8) * 24 + k + 4];
            al[kc][0] = SL[(size_t)r0 * 24 + k];
            al[kc][1] = SL[(size_t)(r0 + 8) * 24 + k];
            al[kc][2] = SL[(size_t)r0 * 24 + k + 4];
            al[kc][3] = SL[(size_t)(r0 + 8) * 24 + k + 4];
        }
    }
    float acc[2][8][4] = {};
    int kbeg = ksl * (NN / KSLC), kend = kbeg + NN / KSLC;
    for (int kb = kbeg; kb < kend; kb += 32) {
        for (int idx = tid; idx < 32 * 6; idx += 256) {
            int r = idx / 6, q = (idx % 6) * 4;
            *(float4*)&Bh[r][q] = *(const float4*)&SH[(size_t)(kb + r) * 24 + q];
            *(float4*)&Bl[r][q] = *(const float4*)&SL[(size_t)(kb + r) * 24 + q];
        }
        if (tid < 32) bK[tid] = g_bits[b * NN + kb + tid];
        {
            int r = tid >> 1, k0 = (tid & 1) * 16;
            const float* zp = &Zt[(size_t)(J + r) * NN + kb + k0];
#pragma unroll
            for (int q = 0; q < 16; q += 4)
                *(float4*)&Bs[r][k0 + q] = *(const float4*)&zp[q];
        }
        __syncthreads();
#pragma unroll
        for (int ntA = 0; ntA < 4; ntA++) {
            float fa[4] = {};
            int nr = ntA * 8 + gr;
#pragma unroll
            for (int kc = 0; kc < 3; kc++) {
                unsigned b0h = f2u(Bh[nr][kc * 8 + gc]), b1h = f2u(Bh[nr][kc * 8 + gc + 4]);
                unsigned b0l = f2u(Bl[nr][kc * 8 + gc]), b1l = f2u(Bl[nr][kc * 8 + gc + 4]);
                unsigned h0 = f2u(ah[kc][0]), h1 = f2u(ah[kc][1]);
                unsigned h2 = f2u(ah[kc][2]), h3 = f2u(ah[kc][3]);
                unsigned l0 = f2u(al[kc][0]), l1 = f2u(al[kc][1]);
                unsigned l2 = f2u(al[kc][2]), l3 = f2u(al[kc][3]);
                mma8(fa, h0, h1, h2, h3, b0h, b1h);
                mma8(fa, h0, h1, h2, h3, b0l, b1l);
                mma8(fa, l0, l1, l2, l3, b0h, b1h);
            }
            int c0 = ntA * 8 + 2 * gc;
            unsigned bj0 = bK[c0], bj1 = bK[c0 + 1];
            float v0 = (bi0 & bj0) ? fmaxf(fa[0], 0.f) : 0.f;
            float v1 = (bi0 & bj1) ? fmaxf(fa[1], 0.f) : 0.f;
            float v2 = (bi1 & bj0) ? fmaxf(fa[2], 0.f) : 0.f;
            float v3 = (bi1 & bj1) ? fmaxf(fa[3], 0.f) : 0.f;
            int r0 = warp * 16 + gr;
            *(float2*)&As[r0][c0] = make_float2(rna_tf32(v0), rna_tf32(v1));
            *(float2*)&As[r0 + 8][c0] = make_float2(rna_tf32(v2), rna_tf32(v3));
        }
        __syncthreads();
#pragma unroll
        for (int ks = 0; ks < 32; ks += 8) {
            unsigned bf[8][2];
#pragma unroll
            for (int nt = 0; nt < 8; nt++) {
                int nr = wn * 64 + nt * 8 + gr;
                bf[nt][0] = f2u(Bs[nr][ks + gc]);
                bf[nt][1] = f2u(Bs[nr][ks + gc + 4]);
            }
#pragma unroll
            for (int mt = 0; mt < 2; mt++) {
                int m0 = wm * 32 + mt * 16 + gr;
                unsigned a0 = f2u(As[m0][ks + gc]);
                unsigned a1 = f2u(As[m0 + 8][ks + gc]);
                unsigned a2 = f2u(As[m0][ks + gc + 4]);
                unsigned a3 = f2u(As[m0 + 8][ks + gc + 4]);
#pragma unroll
                for (int nt = 0; nt < 8; nt++)
                    mma8(acc[mt][nt], a0, a1, a2, a3, bf[nt][0], bf[nt][1]);
            }
        }
        __syncthreads();
    }
    float* O = g_nfp + (size_t)ksl * NFSL + ((size_t)b * NN) * DD;
#pragma unroll
    for (int mt = 0; mt < 2; mt++) {
        int row = I + wm * 32 + mt * 16 + gr;
#pragma unroll
        for (int nt = 0; nt < 8; nt++) {
            int col = J + wn * 64 + nt * 8 + 2 * gc;
            *(float2*)&O[(size_t)row * DD + col] = make_float2(acc[mt][nt][0], acc[mt][nt][1]);
            *(float2*)&O[(size_t)(row + 8) * DD + col] = make_float2(acc[mt][nt][2], acc[mt][nt][3]);
        }
    }
}

// hid[n][o] = relu( (d2[n] * sum_ks nfp) @ w1^T + b1 )
__global__ __launch_bounds__(256) void k_hidden_tc(const float* __restrict__ w1,
                                                   const float* __restrict__ b1) {
    __shared__ float As[128 * GPAD], Bs[64 * GPAD];
    int I = blockIdx.y * 128, J = blockIdx.x * 64;
    int tid = threadIdx.x;
    int warp = tid >> 5, lane = tid & 31;
    int wm = warp & 3, wn = warp >> 2;
    int gr = lane >> 2, gc = lane & 3;
    float acc[2][4][4] = {};
    for (int kb = 0; kb < DD; kb += 16) {
#pragma unroll
        for (int it = 0; it < 2; it++) {
            int idx = tid + it * 256;
            int r = idx >> 2;
            int k4 = (idx & 3) * 4;
            size_t off = (size_t)(I + r) * DD + kb + k4;
            float4 v0 = *(const float4*)&g_nfp[off];
            float4 v1 = *(const float4*)&g_nfp[NFSL + off];
            float4 v2 = *(const float4*)&g_nfp[2 * NFSL + off];
            float4 v3 = *(const float4*)&g_nfp[3 * NFSL + off];
            float d2 = rsqrtf(g_deg2[I + r] + 1e-10f);
            float4 v;
            v.x = rna_tf32((v0.x + v1.x + v2.x + v3.x) * d2);
            v.y = rna_tf32((v0.y + v1.y + v2.y + v3.y) * d2);
            v.z = rna_tf32((v0.z + v1.z + v2.z + v3.z) * d2);
            v.w = rna_tf32((v0.w + v1.w + v2.w + v3.w) * d2);
            *(float4*)&As[r * GPAD + k4] = v;
        }
        {
            int r = tid >> 2;
            int k4 = (tid & 3) * 4;
            float4 v = *(const float4*)&w1[(size_t)(J + r) * DD + kb + k4];
            v.x = rna_tf32(v.x); v.y = rna_tf32(v.y); v.z = rna_tf32(v.z); v.w = rna_tf32(v.w);
            *(float4*)&Bs[r * GPAD + k4] = v;
        }
        __syncthreads();
#pragma unroll
        for (int ks = 0; ks < 16; ks += 8) {
            unsigned bf[4][2];
#pragma unroll
            for (int nt = 0; nt < 4; nt++) {
                int n0 = (wn * 32 + nt * 8 + gr) * GPAD + ks + gc;
                bf[nt][0] = f2u(Bs[n0]); bf[nt][1] = f2u(Bs[n0 + 4]);
            }
#pragma unroll
            for (int mt = 0; mt < 2; mt++) {
                int m0 = (wm * 32 + mt * 16 + gr) * GPAD + ks + gc;
                int m1 = m0 + 8 * GPAD;
                unsigned a0 = f2u(As[m0]), a1 = f2u(As[m1]);
                unsigned a2 = f2u(As[m0 + 4]), a3 = f2u(As[m1 + 4]);
#pragma unroll
                for (int nt = 0; nt < 4; nt++)
                    mma8(acc[mt][nt], a0, a1, a2, a3, bf[nt][0], bf[nt][1]);
            }
        }
        __syncthreads();
    }
#pragma unroll
    for (int mt = 0; mt < 2; mt++) {
        int row = I + wm * 32 + mt * 16 + gr;
#pragma unroll
        for (int nt = 0; nt < 4; nt++) {
            int col = J + wn * 32 + nt * 8 + 2 * gc;
            float bb0 = b1[col], bb1 = b1[col + 1];
            *(float2*)&g_hid[(size_t)row * DD + col] =
                make_float2(fmaxf(acc[mt][nt][0] + bb0, 0.f), fmaxf(acc[mt][nt][1] + bb1, 0.f));
            *(float2*)&g_hid[(size_t)(row + 8) * DD + col] =
                make_float2(fmaxf(acc[mt][nt][2] + bb0, 0.f), fmaxf(acc[mt][nt][3] + bb1, 0.f));
        }
    }
}

// feat_out[b][o2][n] = w2 @ hid^T + b2
__global__ __launch_bounds__(256) void k_featout_tc(const float* __restrict__ w2,
                                                    const float* __restrict__ b2,
                                                    float* __restrict__ out_feat) {
    __shared__ float As[128 * GPAD], Bs[64 * GPAD];
    int I = blockIdx.y * 128;
    int J = blockIdx.x * 64;
    int tid = threadIdx.x;
    int warp = tid >> 5, lane = tid & 31;
    int wm = warp & 3, wn = warp >> 2;
    int gr = lane >> 2, gc = lane & 3;
    float acc[2][4][4] = {};
    for (int kb = 0; kb < DD; kb += 16) {
#pragma unroll
        for (int it = 0; it < 2; it++) {
            int idx = tid + it * 256;
            int r = idx >> 2;
            int k4 = (idx & 3) * 4;
            float4 v = *(const float4*)&w2[(size_t)(I + r) * DD + kb + k4];
            v.x = rna_tf32(v.x); v.y = rna_tf32(v.y); v.z = rna_tf32(v.z); v.w = rna_tf32(v.w);
            *(float4*)&As[r * GPAD + k4] = v;
        }
        {
            int r = tid >> 2;
            int k4 = (tid & 3) * 4;
            float4 v = *(const float4*)&g_hid[(size_t)(J + r) * DD + kb + k4];
            v.x = rna_tf32(v.x); v.y = rna_tf32(v.y); v.z = rna_tf32(v.z); v.w = rna_tf32(v.w);
            *(float4*)&Bs[r * GPAD + k4] = v;
        }
        __syncthreads();
#pragma unroll
        for (int ks = 0; ks < 16; ks += 8) {
            unsigned bf[4][2];
#pragma unroll
            for (int nt = 0; nt < 4; nt++) {
                int n0 = (wn * 32 + nt * 8 + gr) * GPAD + ks + gc;
                bf[nt][0] = f2u(Bs[n0]); bf[nt][1] = f2u(Bs[n0 + 4]);
            }
#pragma unroll
            for (int mt = 0; mt < 2; mt++) {
                int m0 = (wm * 32 + mt * 16 + gr) * GPAD + ks + gc;
                int m1 = m0 + 8 * GPAD;
                unsigned a0 = f2u(As[m0]), a1 = f2u(As[m1]);
                unsigned a2 = f2u(As[m0 + 4]), a3 = f2u(As[m1 + 4]);
#pragma unroll
                for (int nt = 0; nt < 4; nt++)
                    mma8(acc[mt][nt], a0, a1, a2, a3, bf[nt][0], bf[nt][1]);
            }
        }
        __syncthreads();
    }
#pragma unroll
    for (int mt = 0; mt < 2; mt++) {
        int row = I + wm * 32 + mt * 16 + gr;
        float bb0 = b2[row], bb1 = b2[row + 8];
#pragma unroll
        for (int nt = 0; nt < 4; nt++) {
            int colg = J + wn * 32 + nt * 8 + 2 * gc;
            int bidx = colg >> 12;
            int n = colg & (NN - 1);
            *(float2*)&out_feat[((size_t)bidx * DD + row) * NN + n] =
                make_float2(acc[mt][nt][0] + bb0, acc[mt][nt][1] + bb0);
            *(float2*)&out_feat[((size_t)bidx * DD + row + 8) * NN + n] =
                make_float2(acc[mt][nt][2] + bb1, acc[mt][nt][3] + bb1);
        }
    }
}

// ---------------- launch ----------------
extern "C" void kernel_launch(void* const* d_in, const int* in_sizes, int n_in,
                              void* d_out, int out_size) {
    const float* pred   = (const float*)d_in[0];
    const float* feat   = (const float*)d_in[1];
    const float* w_cls1 = (const float*)d_in[2];
    const float* b_cls1 = (const float*)d_in[3];
    const float* w_cls2 = (const float*)d_in[4];
    const float* b_cls2 = (const float*)d_in[5];
    const float* w_pro1 = (const float*)d_in[6];
    const float* b_pro1 = (const float*)d_in[7];
    const float* w_pro2 = (const float*)d_in[8];
    const float* b_pro2 = (const float*)d_in[9];
    const float* cw     = (const float*)d_in[10];

    float* out_pred = (float*)d_out;                        // [2][19][4096]
    float* out_feat = (float*)d_out + (size_t)BB * CC * NN; // [2][256][4096]

    const int gram_smem = 2 * GST2B * (int)sizeof(float);   // 73728 B
    cudaFuncSetAttribute(k_gram_tc, cudaFuncAttributeMaxDynamicSharedMemorySize, gram_smem);

    k_softmax_mask<<<dim3(NN / 256, BB), 256>>>(pred, cw);
    k_sumsq<<<dim3(NN / 256, BB), 256>>>(feat);
    k_transpose_norm<<<dim3(NN / 32, DD / 32, BB), dim3(32, 8)>>>(feat);
    k_gram_tc<<<dim3(NN / 128, NN / 128, BB), 256, gram_smem>>>();
    k_topk<<<dim3(NN, BB), 256>>>();
    k_scale_y<<<dim3(NN / 256, BB), 256>>>(pred);
    k_p2sparse<<<dim3(NN / 8, BB), 256>>>();
    k_predhead<<<dim3(NN / 256, BB), 256>>>(pred, w_cls1, b_cls1, w_cls2, b_cls2, out_pred);
    k_deg2_tc<<<dim3(NN / 128, NN / 128, BB), 256>>>();
    k_scale_zT<<<(BB * DD * NN) / 256, 256>>>(feat);
    k_nf_fused<<<dim3(DD / 128, NN / 128, BB * KSLC), 256>>>();
    k_hidden_tc<<<dim3(DD / 64, (BB * NN) / 128), 256>>>(w_pro1, b_pro1);
    k_featout_tc<<<dim3((BB * NN) / 64, DD / 128), 256>>>(w_pro2, b_pro2, out_feat);
}

// round 17
// speedup vs baseline: 1.0205x; 1.0205x over previous
#include <cuda_runtime.h>
#include <math.h>

#define BB 2
#define CC 19
#define NN 4096
#define DD 256
#define HH 64
#define GPAD 20
#define GSTG (128 * GPAD)
#define GST2 (2 * GSTG)
#define TSTR 132
#define KSLC 4
#define NFSL ((size_t)BB * NN * DD)
#define SCAP 128

// ---------------- scratch ----------------
__device__ float    g_aff [(size_t)BB * NN * NN];
__device__ float    g_nrm [BB * NN];
__device__ float    g_xn  [BB * NN * DD];
__device__ float    g_zT  [BB * DD * NN];
__device__ float    g_nfp [KSLC * (size_t)BB * NN * DD];
__device__ float    g_hid [BB * NN * DD];
__device__ int      g_pmax [BB * NN];
__device__ float    g_mask [BB * NN];
__device__ float    g_thr  [BB * NN];
__device__ float    g_deg  [BB * NN];
__device__ float    g_deg2 [BB * NN];
__device__ float    g_y    [BB * NN * CC];
__device__ float    g_p2   [BB * NN * CC];
__device__ float    g_spnh [BB * NN * 24];
__device__ float    g_spnl [BB * NN * 24];
__device__ unsigned g_bits [BB * NN];
__device__ int      g_sidx [(size_t)BB * NN * SCAP];
__device__ float    g_sval [(size_t)BB * NN * SCAP];
__device__ int      g_scnt [BB * NN];

// ---------------- helpers ----------------
__device__ __forceinline__ float rna_tf32(float x) {
    unsigned u;
    asm("cvt.rna.tf32.f32 %0, %1;" : "=r"(u) : "f"(x));
    return __uint_as_float(u);
}
__device__ __forceinline__ unsigned f2u(float x) { return __float_as_uint(x); }

__device__ __forceinline__ void split_tf32(float x, unsigned& hi, unsigned& lo) {
    float h = rna_tf32(x);
    hi = __float_as_uint(h);
    lo = __float_as_uint(rna_tf32(x - h));
}

__device__ __forceinline__ void mma8(float* c,
                                     unsigned a0, unsigned a1, unsigned a2, unsigned a3,
                                     unsigned b0, unsigned b1) {
    asm volatile(
        "mma.sync.aligned.m16n8k8.row.col.f32.tf32.tf32.f32 "
        "{%0,%1,%2,%3},{%4,%5,%6,%7},{%8,%9},{%0,%1,%2,%3};\n"
        : "+f"(c[0]), "+f"(c[1]), "+f"(c[2]), "+f"(c[3])
        : "r"(a0), "r"(a1), "r"(a2), "r"(a3), "r"(b0), "r"(b1));
}

__device__ __forceinline__ void cp_async16(const void* smem, const void* gmem) {
    unsigned s = (unsigned)__cvta_generic_to_shared(smem);
    asm volatile("cp.async.cg.shared.global [%0], [%1], 16;" :: "r"(s), "l"(gmem));
}

// ---------------- small kernels ----------------
__global__ void k_softmax_mask(const float* __restrict__ pred,
                               const float* __restrict__ cw) {
    int b = blockIdx.y;
    int n = blockIdx.x * 256 + threadIdx.x;
    const float* p = pred + (size_t)b * CC * NN;
    float x[CC];
    float m = -1e30f; int am = 0;
#pragma unroll
    for (int c = 0; c < CC; c++) {
        x[c] = p[c * NN + n];
        if (x[c] > m) { m = x[c]; am = c; }
    }
    float s = 0.f;
#pragma unroll
    for (int c = 0; c < CC; c++) s += expf(x[c] - m);
    float pprob = 1.0f / s;
    float cwmax = cw[0];
#pragma unroll
    for (int c = 1; c < CC; c++) cwmax = fmaxf(cwmax, cw[c]);
    float cwm = cw[am] / (cwmax + 1e-10f) * 0.95f;
    g_pmax[b * NN + n] = am;
    g_mask[b * NN + n] = (pprob >= 0.95f || pprob >= cwm) ? 1.f : 0.f;
    g_deg[b * NN + n] = 0.f;
#pragma unroll
    for (int c = 0; c < CC; c++) g_p2[((size_t)b * NN + n) * CC + c] = 0.f;
}

__global__ void k_sumsq(const float* __restrict__ feat) {
    int b = blockIdx.y;
    int n = blockIdx.x * 256 + threadIdx.x;
    const float* p = feat + (size_t)b * DD * NN + n;
    float s = 0.f;
#pragma unroll 8
    for (int d = 0; d < DD; d++) {
        float v = p[(size_t)d * NN];
        s += v * v;
    }
    g_nrm[b * NN + n] = 1.0f / (sqrtf(s) + 1e-9f);
}

__global__ void k_transpose_norm(const float* __restrict__ feat) {
    __shared__ float t[32][33];
    int b = blockIdx.z;
    int n0 = blockIdx.x * 32, d0 = blockIdx.y * 32;
#pragma unroll
    for (int k = 0; k < 4; k++) {
        int d = d0 + threadIdx.y + 8 * k, n = n0 + threadIdx.x;
        t[threadIdx.y + 8 * k][threadIdx.x] = feat[((size_t)b * DD + d) * NN + n];
    }
    __syncthreads();
#pragma unroll
    for (int k = 0; k < 4; k++) {
        int n = n0 + threadIdx.y + 8 * k, d = d0 + threadIdx.x;
        float v = t[threadIdx.x][threadIdx.y + 8 * k] * g_nrm[b * NN + n];
        g_xn[((size_t)b * NN + n) * DD + d] = v;
    }
}

// ---------------- gram: split-tf32 MMA, triangular, cp.async (k-chunk 16) ----------------
__global__ __launch_bounds__(256) void k_gram_tc() {
    if (blockIdx.x < blockIdx.y) return;
    int b = blockIdx.z;
    const float* X = g_xn + (size_t)b * NN * DD;
    float* Cc = g_aff + (size_t)b * NN * NN;
    extern __shared__ float sm[];
    int I = blockIdx.y * 128, J = blockIdx.x * 128;
    bool offdiag = (blockIdx.x != blockIdx.y);
    int tid = threadIdx.x;
    int warp = tid >> 5, lane = tid & 31;
    int wm = warp & 1, wn = warp >> 1;
    int gr = lane >> 2, gc = lane & 3;

    auto prefetch = [&](int stage, int kb) {
        float* S = sm + stage * GST2;
#pragma unroll
        for (int it = 0; it < 2; it++) {
            int idx = tid + it * 256;
            int r = idx >> 2, k4 = (idx & 3) * 4;
            cp_async16(&S[r * GPAD + k4], &X[(size_t)(I + r) * DD + kb + k4]);
            cp_async16(&S[GSTG + r * GPAD + k4], &X[(size_t)(J + r) * DD + kb + k4]);
        }
    };

    prefetch(0, 0);
    asm volatile("cp.async.commit_group;" ::: "memory");

    float acc[4][4][4] = {};
    for (int i = 0; i < 16; i++) {
        asm volatile("cp.async.wait_group 0;" ::: "memory");
        __syncthreads();
        if (i + 1 < 16) {
            prefetch((i + 1) & 1, (i + 1) * 16);
            asm volatile("cp.async.commit_group;" ::: "memory");
        }
        const float* S = sm + (i & 1) * GST2;
        const float* As = S;
        const float* Bs = S + GSTG;
#pragma unroll
        for (int ks = 0; ks < 16; ks += 8) {
            unsigned bh[4][2], bl[4][2];
#pragma unroll
            for (int nt = 0; nt < 4; nt++) {
                int n0 = (wn * 32 + nt * 8 + gr) * GPAD + ks + gc;
                split_tf32(Bs[n0], bh[nt][0], bl[nt][0]);
                split_tf32(Bs[n0 + 4], bh[nt][1], bl[nt][1]);
            }
#pragma unroll
            for (int mt = 0; mt < 4; mt++) {
                int m0 = (wm * 64 + mt * 16 + gr) * GPAD + ks + gc;
                int m1 = m0 + 8 * GPAD;
                unsigned ah0, ah1, ah2, ah3, al0, al1, al2, al3;
                split_tf32(As[m0], ah0, al0);
                split_tf32(As[m1], ah1, al1);
                split_tf32(As[m0 + 4], ah2, al2);
                split_tf32(As[m1 + 4], ah3, al3);
#pragma unroll
                for (int nt = 0; nt < 4; nt++) {
                    mma8(acc[mt][nt], ah0, ah1, ah2, ah3, bh[nt][0], bh[nt][1]);
                    mma8(acc[mt][nt], ah0, ah1, ah2, ah3, bl[nt][0], bl[nt][1]);
                    mma8(acc[mt][nt], al0, al1, al2, al3, bh[nt][0], bh[nt][1]);
                }
            }
        }
        __syncthreads();
    }
#pragma unroll
    for (int mt = 0; mt < 4; mt++)
#pragma unroll
        for (int nt = 0; nt < 4; nt++)
#pragma unroll
            for (int q = 0; q < 4; q++)
                acc[mt][nt][q] = fmaxf(acc[mt][nt][q], 0.f);
#pragma unroll
    for (int mt = 0; mt < 4; mt++) {
        int row0 = I + wm * 64 + mt * 16 + gr;
#pragma unroll
        for (int nt = 0; nt < 4; nt++) {
            int col = J + wn * 32 + nt * 8 + 2 * gc;
            *(float2*)&Cc[(size_t)row0 * NN + col] = make_float2(acc[mt][nt][0], acc[mt][nt][1]);
            *(float2*)&Cc[(size_t)(row0 + 8) * NN + col] = make_float2(acc[mt][nt][2], acc[mt][nt][3]);
        }
    }
    if (offdiag) {
#pragma unroll
        for (int h = 0; h < 2; h++) {
            __syncthreads();
            if ((wn >> 1) == h) {
                int cb = (wn & 1) * 32;
#pragma unroll
                for (int mt = 0; mt < 4; mt++) {
                    int r = wm * 64 + mt * 16 + gr;
#pragma unroll
                    for (int nt = 0; nt < 4; nt++) {
                        int c = cb + nt * 8 + 2 * gc;
                        sm[c * TSTR + r] = acc[mt][nt][0];
                        sm[(c + 1) * TSTR + r] = acc[mt][nt][1];
                        sm[c * TSTR + r + 8] = acc[mt][nt][2];
                        sm[(c + 1) * TSTR + r + 8] = acc[mt][nt][3];
                    }
                }
            }
            __syncthreads();
            for (int idx = tid; idx < 64 * 32; idx += 256) {
                int c = idx >> 5;
                int q = (idx & 31) * 4;
                float4 v = *(const float4*)&sm[c * TSTR + q];
                *(float4*)&Cc[(size_t)(J + h * 64 + c) * NN + I + q] = v;
            }
        }
    }
}

// per-row 21st-largest via byte-radix select; round-1 hist fused with load;
// fused deg + survivor list emission
__global__ void k_topk() {
    int b = blockIdx.y, row = blockIdx.x;
    const float* A = g_aff + ((size_t)b * NN + row) * NN;
    __shared__ unsigned sv[NN];
    __shared__ int hist[256];
    __shared__ unsigned s_prefix;
    __shared__ int s_k;
    __shared__ int s_cnt;
    int t = threadIdx.x;
    hist[t] = 0;
    if (t == 0) { s_prefix = 0; s_k = 21; s_cnt = 0; }
    __syncthreads();
    for (int i = t; i < NN; i += 256) {
        unsigned v = __float_as_uint(A[i]);
        sv[i] = v;
        atomicAdd(&hist[v >> 24], 1);
    }
    __syncthreads();
    if (t < 32) {
        int base = 255 - t * 8;
        int c[8]; int sum = 0;
#pragma unroll
        for (int j = 0; j < 8; j++) { c[j] = hist[base - j]; sum += c[j]; }
        int incl = sum;
#pragma unroll
        for (int o = 1; o < 32; o <<= 1) {
            int up = __shfl_up_sync(0xffffffffu, incl, o);
            if (t >= o) incl += up;
        }
        int excl = incl - sum;
        int kk = s_k;
        if (excl < kk && incl >= kk) {
            int run = excl;
#pragma unroll
            for (int j = 0; j < 8; j++) {
                run += c[j];
                if (run >= kk) {
                    s_prefix = (unsigned)(base - j) << 24;
                    s_k = kk - (run - c[j]);
                    break;
                }
            }
        }
    }
    __syncthreads();
#pragma unroll
    for (int shift = 16; shift >= 0; shift -= 8) {
        hist[t] = 0;
        __syncthreads();
        unsigned pfx = s_prefix;
        unsigned mask = 0xFFFFFFFFu << (shift + 8);
        for (int i = t; i < NN; i += 256) {
            unsigned v = sv[i];
            if ((v & mask) == pfx) atomicAdd(&hist[(v >> shift) & 255], 1);
        }
        __syncthreads();
        if (t < 32) {
            int base = 255 - t * 8;
            int c[8]; int sum = 0;
#pragma unroll
            for (int j = 0; j < 8; j++) { c[j] = hist[base - j]; sum += c[j]; }
            int incl = sum;
#pragma unroll
            for (int o = 1; o < 32; o <<= 1) {
                int up = __shfl_up_sync(0xffffffffu, incl, o);
                if (t >= o) incl += up;
            }
            int excl = incl - sum;
            int kk = s_k;
            if (excl < kk && incl >= kk) {
                int run = excl;
#pragma unroll
                for (int j = 0; j < 8; j++) {
                    run += c[j];
                    if (run >= kk) {
                        s_prefix = pfx | ((unsigned)(base - j) << shift);
                        s_k = kk - (run - c[j]);
                        break;
                    }
                }
            }
        }
        __syncthreads();
    }
    unsigned thr_bits = s_prefix;
    if (t == 0) g_thr[b * NN + row] = __uint_as_float(thr_bits);
    int*   SI = g_sidx + ((size_t)b * NN + row) * SCAP;
    float* SV = g_sval + ((size_t)b * NN + row) * SCAP;
    float s = 0.f;
    for (int i = t; i < NN; i += 256) {
        unsigned v = sv[i];
        if (v >= thr_bits) {
            float val = __uint_as_float(v);
            s += val;
            atomicAdd(&g_deg[b * NN + i], val);
            int slot = atomicAdd(&s_cnt, 1);
            if (slot < SCAP) { SI[slot] = i; SV[slot] = val; }
        }
    }
#pragma unroll
    for (int o = 16; o; o >>= 1) s += __shfl_down_sync(0xffffffffu, s, o);
    if ((t & 31) == 0) atomicAdd(&g_deg[b * NN + row], s);
    __syncthreads();
    if (t == 0) g_scnt[b * NN + row] = (s_cnt < SCAP) ? s_cnt : SCAP;
}

// y scale + bits signature + deg2 zero (fused)
__global__ void k_scale_y(const float* __restrict__ pred) {
    int b = blockIdx.y;
    int m = blockIdx.x * 256 + threadIdx.x;
    float d1 = rsqrtf(g_deg[b * NN + m] + 1e-10f);
    const float* p = pred + (size_t)b * CC * NN;
#pragma unroll
    for (int c = 0; c < CC; c++)
        g_y[((size_t)b * NN + m) * CC + c] = d1 * p[c * NN + m];
    unsigned bits = 0;
#pragma unroll
    for (int j = 0; j < CC; j++) {
        int L = m * CC + j;
        int w = L / (CC * HH);
        int rem = L - w * (CC * HH);
        int c = rem >> 6;
        int h = rem & 63;
        if (g_pmax[b * NN + (h << 6) + w] == c) bits |= (1u << j);
    }
    g_bits[b * NN + m] = bits;
    g_deg2[b * NN + m] = 0.f;
}

// sparse p2: warp per row; row term local, mirror term via scattered atomics
__global__ __launch_bounds__(256) void k_p2sparse() {
    int b = blockIdx.y;
    int warp = threadIdx.x >> 5, lane = threadIdx.x & 31;
    int row = blockIdx.x * 8 + warp;
    int cnt = g_scnt[b * NN + row];
    const int*   SI = g_sidx + ((size_t)b * NN + row) * SCAP;
    const float* SV = g_sval + ((size_t)b * NN + row) * SCAP;
    float* P = g_p2 + (size_t)b * NN * CC;
    const float* Y = g_y + (size_t)b * NN * CC;
    float yi = (lane < CC) ? Y[(size_t)row * CC + lane] : 0.f;
    float acc = 0.f;
    for (int sidx = 0; sidx < cnt; sidx++) {
        int j = SI[sidx];
        float a = SV[sidx];
        if (lane < CC) {
            acc += a * Y[(size_t)j * CC + lane];
            atomicAdd(&P[(size_t)j * CC + lane], a * yi);
        }
    }
    if (lane < CC) atomicAdd(&P[(size_t)row * CC + lane], acc);
}

__global__ void k_predhead(const float* __restrict__ pred,
                           const float* __restrict__ w1, const float* __restrict__ b1,
                           const float* __restrict__ w2, const float* __restrict__ b2,
                           float* __restrict__ out_pred) {
    __shared__ float W1[CC * CC], W2[CC * CC], B1[CC], B2[CC];
    int t = threadIdx.x;
    for (int i = t; i < CC * CC; i += 256) { W1[i] = w1[i]; W2[i] = w2[i]; }
    if (t < CC) { B1[t] = b1[t]; B2[t] = b2[t]; }
    __syncthreads();
    int b = blockIdx.y;
    int n = blockIdx.x * 256 + t;
    float mk = g_mask[b * NN + n];
    float wa = 0.8f - 0.6f * mk;
    float wb = 0.2f + 0.6f * mk;
    float d1n = rsqrtf(g_deg[b * NN + n] + 1e-10f);
    float v[CC];
#pragma unroll
    for (int c = 0; c < CC; c++) {
        float p2v = g_p2[((size_t)b * NN + n) * CC + c] * d1n;
        float prv = pred[((size_t)b * CC + c) * NN + n];
        v[c] = wa * p2v + wb * prv;
    }
    float t1[CC];
#pragma unroll
    for (int o = 0; o < CC; o++) {
        float s = B1[o];
#pragma unroll
        for (int c = 0; c < CC; c++) s += W1[o * CC + c] * v[c];
        t1[o] = s;
    }
    float u[CC];
    float m = -1e30f;
#pragma unroll
    for (int o = 0; o < CC; o++) {
        float s = B2[o];
#pragma unroll
        for (int c = 0; c < CC; c++) s += W2[o * CC + c] * t1[c];
        u[o] = s;
        out_pred[((size_t)b * CC + o) * NN + n] = s;
        m = fmaxf(m, s);
    }
    float sum = 0.f;
#pragma unroll
    for (int o = 0; o < CC; o++) { u[o] = expf(u[o] - m); sum += u[o]; }
    float inv = 1.0f / sum;
    float nrm = 0.f;
#pragma unroll
    for (int o = 0; o < CC; o++) { u[o] *= inv; nrm += u[o] * u[o]; }
    float rn = 1.0f / (sqrtf(nrm) + 1e-9f);
    size_t base = ((size_t)b * NN + n) * 24;
#pragma unroll
    for (int o = 0; o < CC; o++) {
        float val = u[o] * rn;
        float hi = rna_tf32(val);
        g_spnh[base + o] = hi;
        g_spnl[base + o] = rna_tf32(val - hi);
    }
#pragma unroll
    for (int o = CC; o < 24; o++) { g_spnh[base + o] = 0.f; g_spnl[base + o] = 0.f; }
}

// deg2 = rowsum(AF), AF symmetric -> triangular blocks; off-diag adds col sums
__global__ __launch_bounds__(256) void k_deg2_tc() {
    if (blockIdx.x < blockIdx.y) return;
    int b = blockIdx.z;
    int I = blockIdx.y * 128, J = blockIdx.x * 128;
    bool offdiag = (blockIdx.x != blockIdx.y);
    const float* SH = g_spnh + (size_t)b * NN * 24;
    const float* SL = g_spnl + (size_t)b * NN * 24;
    __shared__ float Bh[128][28], Bl[128][28];
    __shared__ unsigned bJ[128];
    __shared__ float degs[128];
    __shared__ float degsJ[128];
    int tid = threadIdx.x;
    for (int idx = tid; idx < 128 * 6; idx += 256) {
        int r = idx / 6, q = (idx % 6) * 4;
        *(float4*)&Bh[r][q] = *(const float4*)&SH[(size_t)(J + r) * 24 + q];
        *(float4*)&Bl[r][q] = *(const float4*)&SL[(size_t)(J + r) * 24 + q];
    }
    if (tid < 128) { bJ[tid] = g_bits[b * NN + J + tid]; degs[tid] = 0.f; degsJ[tid] = 0.f; }
    int warp = tid >> 5, lane = tid & 31;
    int wm = warp & 3, wn = warp >> 2;
    int gr = lane >> 2, gc = lane & 3;
    float ah[2][3][4], al[2][3][4];
    unsigned bi[2][2];
#pragma unroll
    for (int mt = 0; mt < 2; mt++) {
        int r0 = I + wm * 32 + mt * 16 + gr;
        bi[mt][0] = g_bits[b * NN + r0];
        bi[mt][1] = g_bits[b * NN + r0 + 8];
#pragma unroll
        for (int kc = 0; kc < 3; kc++) {
            int k = kc * 8 + gc;
            ah[mt][kc][0] = SH[(size_t)r0 * 24 + k];
            ah[mt][kc][1] = SH[(size_t)(r0 + 8) * 24 + k];
            ah[mt][kc][2] = SH[(size_t)r0 * 24 + k + 4];
            ah[mt][kc][3] = SH[(size_t)(r0 + 8) * 24 + k + 4];
            al[mt][kc][0] = SL[(size_t)r0 * 24 + k];
            al[mt][kc][1] = SL[(size_t)(r0 + 8) * 24 + k];
            al[mt][kc][2] = SL[(size_t)r0 * 24 + k + 4];
            al[mt][kc][3] = SL[(size_t)(r0 + 8) * 24 + k + 4];
        }
    }
    __syncthreads();
    float rs[2][2] = {};
#pragma unroll
    for (int nt = 0; nt < 8; nt++) {
        int nr = wn * 64 + nt * 8 + gr;
        int c0 = wn * 64 + nt * 8 + 2 * gc;
        unsigned bj0 = bJ[c0], bj1 = bJ[c0 + 1];
        float cs0 = 0.f, cs1 = 0.f;
#pragma unroll
        for (int mt = 0; mt < 2; mt++) {
            float acc[4] = {};
#pragma unroll
            for (int kc = 0; kc < 3; kc++) {
                unsigned bh0 = f2u(Bh[nr][kc * 8 + gc]), bh1 = f2u(Bh[nr][kc * 8 + gc + 4]);
                unsigned bl0 = f2u(Bl[nr][kc * 8 + gc]), bl1 = f2u(Bl[nr][kc * 8 + gc + 4]);
                unsigned h0 = f2u(ah[mt][kc][0]), h1 = f2u(ah[mt][kc][1]);
                unsigned h2 = f2u(ah[mt][kc][2]), h3 = f2u(ah[mt][kc][3]);
                unsigned l0 = f2u(al[mt][kc][0]), l1 = f2u(al[mt][kc][1]);
                unsigned l2 = f2u(al[mt][kc][2]), l3 = f2u(al[mt][kc][3]);
                mma8(acc, h0, h1, h2, h3, bh0, bh1);
                mma8(acc, h0, h1, h2, h3, bl0, bl1);
                mma8(acc, l0, l1, l2, l3, bh0, bh1);
            }
            float v0 = (bi[mt][0] & bj0) ? fmaxf(acc[0], 0.f) : 0.f;
            float v1 = (bi[mt][0] & bj1) ? fmaxf(acc[1], 0.f) : 0.f;
            float v2 = (bi[mt][1] & bj0) ? fmaxf(acc[2], 0.f) : 0.f;
            float v3 = (bi[mt][1] & bj1) ? fmaxf(acc[3], 0.f) : 0.f;
            rs[mt][0] += v0 + v1;
            rs[mt][1] += v2 + v3;
            cs0 += v0 + v2;
            cs1 += v1 + v3;
        }
        if (offdiag) {
#pragma unroll
            for (int o = 16; o >= 4; o >>= 1) {
                cs0 += __shfl_down_sync(0xffffffffu, cs0, o);
                cs1 += __shfl_down_sync(0xffffffffu, cs1, o);
            }
            if (gr == 0) {
                atomicAdd(&degsJ[c0], cs0);
                atomicAdd(&degsJ[c0 + 1], cs1);
            }
        }
    }
#pragma unroll
    for (int mt = 0; mt < 2; mt++)
#pragma unroll
        for (int h = 0; h < 2; h++) {
            float v = rs[mt][h];
            v += __shfl_down_sync(0xffffffffu, v, 2);
            v += __shfl_down_sync(0xffffffffu, v, 1);
            if (gc == 0) atomicAdd(&degs[wm * 32 + mt * 16 + gr + h * 8], v);
        }
    __syncthreads();
    if (tid < 128) {
        atomicAdd(&g_deg2[b * NN + I + tid], degs[tid]);
        if (offdiag) atomicAdd(&g_deg2[b * NN + J + tid], degsJ[tid]);
    }
}

__global__ void k_scale_zT(const float* __restrict__ feat) {
    size_t idx = (size_t)blockIdx.x * 256 + threadIdx.x;
    size_t m = idx & (NN - 1);
    size_t b = idx >> 20;
    float d2 = rsqrtf(g_deg2[b * NN + m] + 1e-10f);
    g_zT[idx] = rna_tf32(feat[idx] * d2);
}

// nf partials (split-K): g_nfp[ks] = AF[:, slice] @ z[slice, :]
__global__ __launch_bounds__(256) void k_nf_fused() {
    int zb = blockIdx.z;
    int b = zb >> 2, ksl = zb & 3;
    const float* SH = g_spnh + (size_t)b * NN * 24;
    const float* SL = g_spnl + (size_t)b * NN * 24;
    const float* Zt = g_zT + (size_t)b * DD * NN;
    __shared__ float Bh[32][28], Bl[32][28];
    __shared__ unsigned bK[32];
    __shared__ float As[128][36];
    __shared__ float Bs[128][36];
    int I = blockIdx.y * 128, J = blockIdx.x * 128;
    int tid = threadIdx.x;
    int warp = tid >> 5, lane = tid & 31;
    int wm = warp & 3, wn = warp >> 2;
    int gr = lane >> 2, gc = lane & 3;
    float ah[3][4], al[3][4];
    unsigned bi0, bi1;
    {
        int r0 = I + warp * 16 + gr;
        bi0 = g_bits[b * NN + r0];
        bi1 = g_bits[b * NN + r0 + 8];
#pragma unroll
        for (int kc = 0; kc < 3; kc++) {
            int k = kc * 8 + gc;
            ah[kc][0] = SH[(size_t)r0 * 24 + k];
            ah[kc][1] = SH[(size_t)(r0 + 8) * 24 + k];
            ah[kc][2] = SH[(size_t)r0 * 24 + k + 4];
            ah[kc][3] = SH[(size_t)(r0 + 8) * 24 + k + 4];
            al[kc][0] = SL[(size_t)r0 * 24 + k];
            al[kc][1] = SL[(size_t)(r0 + 8) * 24 + k];
            al[kc][2] = SL[(size_t)r0 * 24 + k + 4];
            al[kc][3] = SL[(size_t)(r0 + 8) * 24 + k + 4];
        }
    }
    float acc[2][8][4] = {};
    int kbeg = ksl * (NN / KSLC), kend = kbeg + NN / KSLC;
    for (int kb = kbeg; kb < kend; kb += 32) {
        for (int idx = tid; idx < 32 * 6; idx += 256) {
            int r = idx / 6, q = (idx % 6) * 4;
            *(float4*)&Bh[r][q] = *(const float4*)&SH[(size_t)(kb + r) * 24 + q];
            *(float4*)&Bl[r][q] = *(const float4*)&SL[(size_t)(kb + r) * 24 + q];
        }
        if (tid < 32) bK[tid] = g_bits[b * NN + kb + tid];
        {
            int r = tid >> 1, k0 = (tid & 1) * 16;
            const float* zp = &Zt[(size_t)(J + r) * NN + kb + k0];
#pragma unroll
            for (int q = 0; q < 16; q += 4)
                *(float4*)&Bs[r][k0 + q] = *(const float4*)&zp[q];
        }
        __syncthreads();
#pragma unroll
        for (int ntA = 0; ntA < 4; ntA++) {
            float fa[4] = {};
            int nr = ntA * 8 + gr;
#pragma unroll
            for (int kc = 0; kc < 3; kc++) {
                unsigned b0h = f2u(Bh[nr][kc * 8 + gc]), b1h = f2u(Bh[nr][kc * 8 + gc + 4]);
                unsigned b0l = f2u(Bl[nr][kc * 8 + gc]), b1l = f2u(Bl[nr][kc * 8 + gc + 4]);
                unsigned h0 = f2u(ah[kc][0]), h1 = f2u(ah[kc][1]);
                unsigned h2 = f2u(ah[kc][2]), h3 = f2u(ah[kc][3]);
                unsigned l0 = f2u(al[kc][0]), l1 = f2u(al[kc][1]);
                unsigned l2 = f2u(al[kc][2]), l3 = f2u(al[kc][3]);
                mma8(fa, h0, h1, h2, h3, b0h, b1h);
                mma8(fa, h0, h1, h2, h3, b0l, b1l);
                mma8(fa, l0, l1, l2, l3, b0h, b1h);
            }
            int c0 = ntA * 8 + 2 * gc;
            unsigned bj0 = bK[c0], bj1 = bK[c0 + 1];
            float v0 = (bi0 & bj0) ? fmaxf(fa[0], 0.f) : 0.f;
            float v1 = (bi0 & bj1) ? fmaxf(fa[1], 0.f) : 0.f;
            float v2 = (bi1 & bj0) ? fmaxf(fa[2], 0.f) : 0.f;
            float v3 = (bi1 & bj1) ? fmaxf(fa[3], 0.f) : 0.f;
            int r0 = warp * 16 + gr;
            *(float2*)&As[r0][c0] = make_float2(rna_tf32(v0), rna_tf32(v1));
            *(float2*)&As[r0 + 8][c0] = make_float2(rna_tf32(v2), rna_tf32(v3));
        }
        __syncthreads();
#pragma unroll
        for (int ks = 0; ks < 32; ks += 8) {
            unsigned bf[8][2];
#pragma unroll
            for (int nt = 0; nt < 8; nt++) {
                int nr = wn * 64 + nt * 8 + gr;
                bf[nt][0] = f2u(Bs[nr][ks + gc]);
                bf[nt][1] = f2u(Bs[nr][ks + gc + 4]);
            }
#pragma unroll
            for (int mt = 0; mt < 2; mt++) {
                int m0 = wm * 32 + mt * 16 + gr;
                unsigned a0 = f2u(As[m0][ks + gc]);
                unsigned a1 = f2u(As[m0 + 8][ks + gc]);
                unsigned a2 = f2u(As[m0][ks + gc + 4]);
                unsigned a3 = f2u(As[m0 + 8][ks + gc + 4]);
#pragma unroll
                for (int nt = 0; nt < 8; nt++)
                    mma8(acc[mt][nt], a0, a1, a2, a3, bf[nt][0], bf[nt][1]);
            }
        }
        __syncthreads();
    }
    float* O = g_nfp + (size_t)ksl * NFSL + ((size_t)b * NN) * DD;
#pragma unroll
    for (int mt = 0; mt < 2; mt++) {
        int row = I + wm * 32 + mt * 16 + gr;
#pragma unroll
        for (int nt = 0; nt < 8; nt++) {
            int col = J + wn * 64 + nt * 8 + 2 * gc;
            *(float2*)&O[(size_t)row * DD + col] = make_float2(acc[mt][nt][0], acc[mt][nt][1]);
            *(float2*)&O[(size_t)(row + 8) * DD + col] = make_float2(acc[mt][nt][2], acc[mt][nt][3]);
        }
    }
}

// hid[n][o] = relu( (d2[n] * sum_ks nfp) @ w1^T + b1 )
__global__ __launch_bounds__(256) void k_hidden_tc(const float* __restrict__ w1,
                                                   const float* __restrict__ b1) {
    __shared__ float As[128 * GPAD], Bs[64 * GPAD];
    int I = blockIdx.y * 128, J = blockIdx.x * 64;
    int tid = threadIdx.x;
    int warp = tid >> 5, lane = tid & 31;
    int wm = warp & 3, wn = warp >> 2;
    int gr = lane >> 2, gc = lane & 3;
    float acc[2][4][4] = {};
    for (int kb = 0; kb < DD; kb += 16) {
#pragma unroll
        for (int it = 0; it < 2; it++) {
            int idx = tid + it * 256;
            int r = idx >> 2;
            int k4 = (idx & 3) * 4;
            size_t off = (size_t)(I + r) * DD + kb + k4;
            float4 v0 = *(const float4*)&g_nfp[off];
            float4 v1 = *(const float4*)&g_nfp[NFSL + off];
            float4 v2 = *(const float4*)&g_nfp[2 * NFSL + off];
            float4 v3 = *(const float4*)&g_nfp[3 * NFSL + off];
            float d2 = rsqrtf(g_deg2[I + r] + 1e-10f);
            float4 v;
            v.x = rna_tf32((v0.x + v1.x + v2.x + v3.x) * d2);
            v.y = rna_tf32((v0.y + v1.y + v2.y + v3.y) * d2);
            v.z = rna_tf32((v0.z + v1.z + v2.z + v3.z) * d2);
            v.w = rna_tf32((v0.w + v1.w + v2.w + v3.w) * d2);
            *(float4*)&As[r * GPAD + k4] = v;
        }
        {
            int r = tid >> 2;
            int k4 = (tid & 3) * 4;
            float4 v = *(const float4*)&w1[(size_t)(J + r) * DD + kb + k4];
            v.x = rna_tf32(v.x); v.y = rna_tf32(v.y); v.z = rna_tf32(v.z); v.w = rna_tf32(v.w);
            *(float4*)&Bs[r * GPAD + k4] = v;
        }
        __syncthreads();
#pragma unroll
        for (int ks = 0; ks < 16; ks += 8) {
            unsigned bf[4][2];
#pragma unroll
            for (int nt = 0; nt < 4; nt++) {
                int n0 = (wn * 32 + nt * 8 + gr) * GPAD + ks + gc;
                bf[nt][0] = f2u(Bs[n0]); bf[nt][1] = f2u(Bs[n0 + 4]);
            }
#pragma unroll
            for (int mt = 0; mt < 2; mt++) {
                int m0 = (wm * 32 + mt * 16 + gr) * GPAD + ks + gc;
                int m1 = m0 + 8 * GPAD;
                unsigned a0 = f2u(As[m0]), a1 = f2u(As[m1]);
                unsigned a2 = f2u(As[m0 + 4]), a3 = f2u(As[m1 + 4]);
#pragma unroll
                for (int nt = 0; nt < 4; nt++)
                    mma8(acc[mt][nt], a0, a1, a2, a3, bf[nt][0], bf[nt][1]);
            }
        }
        __syncthreads();
    }
#pragma unroll
    for (int mt = 0; mt < 2; mt++) {
        int row = I + wm * 32 + mt * 16 + gr;
#pragma unroll
        for (int nt = 0; nt < 4; nt++) {
            int col = J + wn * 32 + nt * 8 + 2 * gc;
            float bb0 = b1[col], bb1 = b1[col + 1];
            *(float2*)&g_hid[(size_t)row * DD + col] =
                make_float2(fmaxf(acc[mt][nt][0] + bb0, 0.f), fmaxf(acc[mt][nt][1] + bb1, 0.f));
            *(float2*)&g_hid[(size_t)(row + 8) * DD + col] =
                make_float2(fmaxf(acc[mt][nt][2] + bb0, 0.f), fmaxf(acc[mt][nt][3] + bb1, 0.f));
        }
    }
}

// feat_out[b][o2][n] = w2 @ hid^T + b2
__global__ __launch_bounds__(256) void k_featout_tc(const float* __restrict__ w2,
                                                    const float* __restrict__ b2,
                                                    float* __restrict__ out_feat) {
    __shared__ float As[128 * GPAD], Bs[64 * GPAD];
    int I = blockIdx.y * 128;
    int J = blockIdx.x * 64;
    int tid = threadIdx.x;
    int warp = tid >> 5, lane = tid & 31;
    int wm = warp & 3, wn = warp >> 2;
    int gr = lane >> 2, gc = lane & 3;
    float acc[2][4][4] = {};
    for (int kb = 0; kb < DD; kb += 16) {
#pragma unroll
        for (int it = 0; it < 2; it++) {
            int idx = tid + it * 256;
            int r = idx >> 2;
            int k4 = (idx & 3) * 4;
            float4 v = *(const float4*)&w2[(size_t)(I + r) * DD + kb + k4];
            v.x = rna_tf32(v.x); v.y = rna_tf32(v.y); v.z = rna_tf32(v.z); v.w = rna_tf32(v.w);
            *(float4*)&As[r * GPAD + k4] = v;
        }
        {
            int r = tid >> 2;
            int k4 = (tid & 3) * 4;
            float4 v = *(const float4*)&g_hid[(size_t)(J + r) * DD + kb + k4];
            v.x = rna_tf32(v.x); v.y = rna_tf32(v.y); v.z = rna_tf32(v.z); v.w = rna_tf32(v.w);
            *(float4*)&Bs[r * GPAD + k4] = v;
        }
        __syncthreads();
#pragma unroll
        for (int ks = 0; ks < 16; ks += 8) {
            unsigned bf[4][2];
#pragma unroll
            for (int nt = 0; nt < 4; nt++) {
                int n0 = (wn * 32 + nt * 8 + gr) * GPAD + ks + gc;
                bf[nt][0] = f2u(Bs[n0]); bf[nt][1] = f2u(Bs[n0 + 4]);
            }
#pragma unroll
            for (int mt = 0; mt < 2; mt++) {
                int m0 = (wm * 32 + mt * 16 + gr) * GPAD + ks + gc;
                int m1 = m0 + 8 * GPAD;
                unsigned a0 = f2u(As[m0]), a1 = f2u(As[m1]);
                unsigned a2 = f2u(As[m0 + 4]), a3 = f2u(As[m1 + 4]);
#pragma unroll
                for (int nt = 0; nt < 4; nt++)
                    mma8(acc[mt][nt], a0, a1, a2, a3, bf[nt][0], bf[nt][1]);
            }
        }
        __syncthreads();
    }
#pragma unroll
    for (int mt = 0; mt < 2; mt++) {
        int row = I + wm * 32 + mt * 16 + gr;
        float bb0 = b2[row], bb1 = b2[row + 8];
#pragma unroll
        for (int nt = 0; nt < 4; nt++) {
            int colg = J + wn * 32 + nt * 8 + 2 * gc;
            int bidx = colg >> 12;
            int n = colg & (NN - 1);
            *(float2*)&out_feat[((size_t)bidx * DD + row) * NN + n] =
                make_float2(acc[mt][nt][0] + bb0, acc[mt][nt][1] + bb0);
            *(float2*)&out_feat[((size_t)bidx * DD + row + 8) * NN + n] =
                make_float2(acc[mt][nt][2] + bb1, acc[mt][nt][3] + bb1);
        }
    }
}

// ---------------- launch ----------------
extern "C" void kernel_launch(void* const* d_in, const int* in_sizes, int n_in,
                              void* d_out, int out_size) {
    const float* pred   = (const float*)d_in[0];
    const float* feat   = (const float*)d_in[1];
    const float* w_cls1 = (const float*)d_in[2];
    const float* b_cls1 = (const float*)d_in[3];
    const float* w_cls2 = (const float*)d_in[4];
    const float* b_cls2 = (const float*)d_in[5];
    const float* w_pro1 = (const float*)d_in[6];
    const float* b_pro1 = (const float*)d_in[7];
    const float* w_pro2 = (const float*)d_in[8];
    const float* b_pro2 = (const float*)d_in[9];
    const float* cw     = (const float*)d_in[10];

    float* out_pred = (float*)d_out;                        // [2][19][4096]
    float* out_feat = (float*)d_out + (size_t)BB * CC * NN; // [2][256][4096]

    const int gram_smem = 2 * GST2 * (int)sizeof(float);    // 40960 B
    cudaFuncSetAttribute(k_gram_tc, cudaFuncAttributeMaxDynamicSharedMemorySize, gram_smem);

    k_softmax_mask<<<dim3(NN / 256, BB), 256>>>(pred, cw);
    k_sumsq<<<dim3(NN / 256, BB), 256>>>(feat);
    k_transpose_norm<<<dim3(NN / 32, DD / 32, BB), dim3(32, 8)>>>(feat);
    k_gram_tc<<<dim3(NN / 128, NN / 128, BB), 256, gram_smem>>>();
    k_topk<<<dim3(NN, BB), 256>>>();
    k_scale_y<<<dim3(NN / 256, BB), 256>>>(pred);
    k_p2sparse<<<dim3(NN / 8, BB), 256>>>();
    k_predhead<<<dim3(NN / 256, BB), 256>>>(pred, w_cls1, b_cls1, w_cls2, b_cls2, out_pred);
    k_deg2_tc<<<dim3(NN / 128, NN / 128, BB), 256>>>();
    k_scale_zT<<<(BB * DD * NN) / 256, 256>>>(feat);
    k_nf_fused<<<dim3(DD / 128, NN / 128, BB * KSLC), 256>>>();
    k_hidden_tc<<<dim3(DD / 64, (BB * NN) / 128), 256>>>(w_pro1, b_pro1);
    k_featout_tc<<<dim3((BB * NN) / 64, DD / 128), 256>>>(w_pro2, b_pro2, out_feat);
}